// round 12
// baseline (speedup 1.0000x reference)
#include <cuda_runtime.h>
#include <math.h>

#define Bn 8
#define Nn 256
#define Dd 256
#define DHh 64
#define BND (Bn * Nn * DHh)      // 131072
#define BNr (Bn * Nn)            // 2048

// scratch: Qn,Kn,Vn,Q,K,V
__device__ float g_np[6 * BND];
// folded-weight per-row vectors
__device__ float g_u[BNr * Dd];
__device__ float g_v[BNr * Dd];
__device__ float g_c[BNr];
__device__ float g_d[BNr];
// transposed weights (h-major)
__device__ float g_Wkt[DHh * Dd];
__device__ float g_Wqt[DHh * Dd];
// folded 256x256 matrices and bias vectors
__device__ float g_M1[Dd * Dd];    // W_n2e_q @ W_n2e_k^T  (k-major)
__device__ float g_M2[Dd * Dd];    // W_e2n_k @ W_e2n_q^T
__device__ float g_bu[Dd];
__device__ float g_bv[Dd];

__device__ __forceinline__ float warp_sum32(float v) {
    #pragma unroll
    for (int o = 16; o; o >>= 1) v += __shfl_xor_sync(0xffffffffu, v, o);
    return v;
}

// ------------------------------------------------------------------
// transpose: g_Wkt[h][d] = Wk[d][h]; g_Wqt[h][d] = Wq[d][h]
// grid 64, block 256
// ------------------------------------------------------------------
__global__ void transpose_w_kernel(const float* __restrict__ Wk,
                                   const float* __restrict__ Wq)
{
    int h = blockIdx.x;
    int d = threadIdx.x;
    g_Wkt[h * Dd + d] = Wk[d * DHh + h];
    g_Wqt[h * Dd + d] = Wq[d * DHh + h];
}

// ------------------------------------------------------------------
// fold: M1[k][d] = sum_h Wq_n2e[k][h] * Wkt[h][d]
//       M2[k][d] = sum_h Wk_e2n[k][h] * Wqt[h][d]
//       (block 64): bu[d] = sum_h bq_n2e[h]*Wkt[h][d]; bv likewise
// grid 65, block 256
// ------------------------------------------------------------------
__global__ void fold_kernel(const float* __restrict__ Wq_n2e,
                            const float* __restrict__ Wk_e2n,
                            const float* __restrict__ bq_n2e,
                            const float* __restrict__ bk_e2n)
{
    int t = threadIdx.x;
    if (blockIdx.x == 64) {
        float au = 0.f, av = 0.f;
        #pragma unroll 4
        for (int h = 0; h < DHh; ++h) {
            au = fmaf(bq_n2e[h], g_Wkt[h * Dd + t], au);
            av = fmaf(bk_e2n[h], g_Wqt[h * Dd + t], av);
        }
        g_bu[t] = au;
        g_bv[t] = av;
        return;
    }
    int k0 = blockIdx.x * 4;
    __shared__ float wq_s[4][DHh];
    __shared__ float wk_s[4][DHh];
    {
        int row = t >> 6, h = t & 63;
        wq_s[row][h] = Wq_n2e[(k0 + row) * DHh + h];
        wk_s[row][h] = Wk_e2n[(k0 + row) * DHh + h];
    }
    __syncthreads();

    float a1[4], a2[4];
    #pragma unroll
    for (int i = 0; i < 4; ++i) { a1[i] = 0.f; a2[i] = 0.f; }
    #pragma unroll 4
    for (int h = 0; h < DHh; ++h) {
        float wk = g_Wkt[h * Dd + t];
        float wq = g_Wqt[h * Dd + t];
        #pragma unroll
        for (int i = 0; i < 4; ++i) {
            a1[i] = fmaf(wq_s[i][h], wk, a1[i]);
            a2[i] = fmaf(wk_s[i][h], wq, a2[i]);
        }
    }
    #pragma unroll
    for (int i = 0; i < 4; ++i) {
        g_M1[(k0 + i) * Dd + t] = a1[i];
        g_M2[(k0 + i) * Dd + t] = a2[i];
    }
}

// ------------------------------------------------------------------
// mega-proj: grid (128 row-tiles, 14), block 256. 16 rows/block.
//   y 0..5  : 64-wide projections into g_np slots (y0 also c, y1 also d)
//   y 6..9  : u quarter (d0=(y-6)*64) via g_M1 (+g_bu)
//   y 10..13: v quarter via g_M2 (+g_bv)
// ------------------------------------------------------------------
__global__ void megaproj_kernel(
    const float* __restrict__ x, const float* __restrict__ mask,
    const float* __restrict__ W0, const float* __restrict__ b0,
    const float* __restrict__ W1, const float* __restrict__ b1,
    const float* __restrict__ W2, const float* __restrict__ b2,
    const float* __restrict__ W3, const float* __restrict__ b3,
    const float* __restrict__ W4, const float* __restrict__ b4,
    const float* __restrict__ W5, const float* __restrict__ b5,
    const float* __restrict__ bk_n2e,   // for c = bk . Qn
    const float* __restrict__ bq_e2n)   // for d = bq . Kn
{
    int p  = blockIdx.y;
    int t  = threadIdx.x;
    int r0 = blockIdx.x * 16;

    __shared__ float xs[16][Dd];
    __shared__ float msk[16];
    __shared__ float cred[8][4];

    {
        const float4* src = reinterpret_cast<const float4*>(x + (size_t)r0 * Dd);
        float4* dst = reinterpret_cast<float4*>(&xs[0][0]);
        #pragma unroll
        for (int i = 0; i < 4; ++i)
            dst[t + i * 256] = src[t + i * 256];
        if (t < 16) msk[t] = mask[r0 + t];
    }
    __syncthreads();

    int h = t & 63, rg = t >> 6;
    int rb = rg * 4;
    int wid = t >> 5, lane = t & 31;

    if (p < 6) {
        const float* W;
        const float* bb;
        switch (p) {
            case 0: W = W0; bb = b0; break;
            case 1: W = W1; bb = b1; break;
            case 2: W = W2; bb = b2; break;
            case 3: W = W3; bb = b3; break;
            case 4: W = W4; bb = b4; break;
            default: W = W5; bb = b5; break;
        }
        float bias = bb[h];
        float a0 = bias, a1 = bias, a2 = bias, a3 = bias;
        #pragma unroll 2
        for (int k = 0; k < Dd; k += 4) {
            float w0 = W[(k + 0) * DHh + h];
            float w1 = W[(k + 1) * DHh + h];
            float w2 = W[(k + 2) * DHh + h];
            float w3 = W[(k + 3) * DHh + h];
            float4 x0 = *reinterpret_cast<const float4*>(&xs[rb + 0][k]);
            float4 x1 = *reinterpret_cast<const float4*>(&xs[rb + 1][k]);
            float4 x2 = *reinterpret_cast<const float4*>(&xs[rb + 2][k]);
            float4 x3 = *reinterpret_cast<const float4*>(&xs[rb + 3][k]);
            a0 = fmaf(x0.x, w0, a0); a0 = fmaf(x0.y, w1, a0);
            a0 = fmaf(x0.z, w2, a0); a0 = fmaf(x0.w, w3, a0);
            a1 = fmaf(x1.x, w0, a1); a1 = fmaf(x1.y, w1, a1);
            a1 = fmaf(x1.z, w2, a1); a1 = fmaf(x1.w, w3, a1);
            a2 = fmaf(x2.x, w0, a2); a2 = fmaf(x2.y, w1, a2);
            a2 = fmaf(x2.z, w2, a2); a2 = fmaf(x2.w, w3, a2);
            a3 = fmaf(x3.x, w0, a3); a3 = fmaf(x3.y, w1, a3);
            a3 = fmaf(x3.z, w2, a3); a3 = fmaf(x3.w, w3, a3);
        }
        float m0 = a0 * msk[rb + 0];
        float m1 = a1 * msk[rb + 1];
        float m2 = a2 * msk[rb + 2];
        float m3 = a3 * msk[rb + 3];
        float* dst = g_np + (size_t)p * BND + (size_t)(r0 + rb) * DHh + h;
        dst[0 * DHh] = m0;
        dst[1 * DHh] = m1;
        dst[2 * DHh] = m2;
        dst[3 * DHh] = m3;

        // bias dots: slot0 -> g_c (bk_n2e . Qn), slot1 -> g_d (bq_e2n . Kn)
        if (p < 2) {
            const float* bvec = (p == 0) ? bk_n2e : bq_e2n;
            float bh = bvec[h];
            float v0 = warp_sum32(bh * m0);
            float v1 = warp_sum32(bh * m1);
            float v2 = warp_sum32(bh * m2);
            float v3 = warp_sum32(bh * m3);
            if (lane == 0) {
                cred[wid][0] = v0; cred[wid][1] = v1;
                cred[wid][2] = v2; cred[wid][3] = v3;
            }
            __syncthreads();
            if (t < 16) {
                int rr = t >> 2, ii = t & 3;
                float val = cred[2 * rr][ii] + cred[2 * rr + 1][ii];
                if (p == 0) g_c[r0 + rr * 4 + ii] = val;
                else        g_d[r0 + rr * 4 + ii] = val;
            }
        }
        return;
    }

    // u/v quarters
    bool is_u = (p < 10);
    int q = is_u ? (p - 6) : (p - 10);
    int d = q * 64 + h;
    const float* M  = is_u ? g_M1 : g_M2;
    float bias = is_u ? g_bu[d] : g_bv[d];
    float a0 = bias, a1 = bias, a2 = bias, a3 = bias;
    #pragma unroll 2
    for (int k = 0; k < Dd; k += 4) {
        float w0 = M[(k + 0) * Dd + d];
        float w1 = M[(k + 1) * Dd + d];
        float w2 = M[(k + 2) * Dd + d];
        float w3 = M[(k + 3) * Dd + d];
        float4 x0 = *reinterpret_cast<const float4*>(&xs[rb + 0][k]);
        float4 x1 = *reinterpret_cast<const float4*>(&xs[rb + 1][k]);
        float4 x2 = *reinterpret_cast<const float4*>(&xs[rb + 2][k]);
        float4 x3 = *reinterpret_cast<const float4*>(&xs[rb + 3][k]);
        a0 = fmaf(x0.x, w0, a0); a0 = fmaf(x0.y, w1, a0);
        a0 = fmaf(x0.z, w2, a0); a0 = fmaf(x0.w, w3, a0);
        a1 = fmaf(x1.x, w0, a1); a1 = fmaf(x1.y, w1, a1);
        a1 = fmaf(x1.z, w2, a1); a1 = fmaf(x1.w, w3, a1);
        a2 = fmaf(x2.x, w0, a2); a2 = fmaf(x2.y, w1, a2);
        a2 = fmaf(x2.z, w2, a2); a2 = fmaf(x2.w, w3, a2);
        a3 = fmaf(x3.x, w0, a3); a3 = fmaf(x3.y, w1, a3);
        a3 = fmaf(x3.z, w2, a3); a3 = fmaf(x3.w, w3, a3);
    }
    float* dst = is_u ? g_u : g_v;
    dst += (size_t)(r0 + rb) * Dd + d;
    dst[0 * Dd] = a0 * msk[rb + 0];
    dst[1 * Dd] = a1 * msk[rb + 1];
    dst[2 * Dd] = a2 * msk[rb + 2];
    dst[3 * Dd] = a3 * msk[rb + 3];
}

// ------------------------------------------------------------------
// Fused mega-kernel (VERBATIM R5/R8/R10, measured ~198us)
// ------------------------------------------------------------------
__global__ void __launch_bounds__(256, 4) fused_kernel(
    const float* __restrict__ e, const float* __restrict__ mask,
    const float* __restrict__ Wv, const float* __restrict__ bv,
    const float* __restrict__ Wmix, const float* __restrict__ bmix,
    float* __restrict__ out_e, float* __restrict__ out_x)
{
    int r = blockIdx.x;
    int b = r >> 8;
    int t = threadIdx.x;
    int wid = t >> 5, lane = t & 31;

    __shared__ float big[128 * 65];
    __shared__ float maskb_s[Nn];
    __shared__ float djs_s[Nn];
    __shared__ float mw[8], lw[8], tw[8];
    __shared__ float gsrow[Dd];
    __shared__ float gt_s;
    __shared__ float Q_s[DHh];
    __shared__ float att[Nn];
    __shared__ float red[256];
    __shared__ float part[4][DHh];
    __shared__ float xsf_s[DHh], xc_s[DHh];

    const float* Vn = g_np + 2 * (size_t)BND;

    maskb_s[t] = mask[b * Nn + t];
    djs_s[t]   = g_d[b * Nn + t];
    __syncthreads();

    int d0 = 4 * lane;
    int d1 = 128 + 4 * lane;

    const float4 u0  = *reinterpret_cast<const float4*>(g_u + (size_t)r * Dd + d0);
    const float4 u1  = *reinterpret_cast<const float4*>(g_u + (size_t)r * Dd + d1);
    const float4 vi0 = *reinterpret_cast<const float4*>(g_v + (size_t)r * Dd + d0);
    const float4 vi1 = *reinterpret_cast<const float4*>(g_v + (size_t)r * Dd + d1);
    const float c_i  = g_c[r];
    const float di   = g_d[r];
    const float xm_i = mask[r];
    const float2 vni = *reinterpret_cast<const float2*>(Vn + (size_t)r * DHh + 2 * lane);

    float m = -INFINITY, l = 0.f, tacc = 0.f;
    float4 s0 = make_float4(0.f, 0.f, 0.f, 0.f);
    float4 s1 = make_float4(0.f, 0.f, 0.f, 0.f);

    const float* erow = e + (size_t)r * Nn * Dd;

    int j = wid;
    float4 e0 = __ldcs(reinterpret_cast<const float4*>(erow + (size_t)j * Dd + d0));
    float4 e1 = __ldcs(reinterpret_cast<const float4*>(erow + (size_t)j * Dd + d1));

    for (; j < Nn; ) {
        int jn = j + 8;
        float4 ne0, ne1;
        if (jn < Nn) {
            ne0 = __ldcs(reinterpret_cast<const float4*>(erow + (size_t)jn * Dd + d0));
            ne1 = __ldcs(reinterpret_cast<const float4*>(erow + (size_t)jn * Dd + d1));
        }
        float4 vj0 = *reinterpret_cast<const float4*>(g_v + (size_t)(b * Nn + j) * Dd + d0);
        float4 vj1 = *reinterpret_cast<const float4*>(g_v + (size_t)(b * Nn + j) * Dd + d1);
        float2 vnj = *reinterpret_cast<const float2*>(Vn + (size_t)(b * Nn + j) * DHh + 2 * lane);
        float xm_j = maskb_s[j];
        float dj   = djs_s[j];

        float4 w0, w1;
        w0.x = vj0.x - vi0.x; w0.y = vj0.y - vi0.y;
        w0.z = vj0.z - vi0.z; w0.w = vj0.w - vi0.w;
        w1.x = vj1.x - vi1.x; w1.y = vj1.y - vi1.y;
        w1.z = vj1.z - vi1.z; w1.w = vj1.w - vi1.w;

        float dot0, dotd;
        dot0 = e0.x * u0.x;              dot0 = fmaf(e0.y, u0.y, dot0);
        dot0 = fmaf(e0.z, u0.z, dot0);   dot0 = fmaf(e0.w, u0.w, dot0);
        dot0 = fmaf(e1.x, u1.x, dot0);   dot0 = fmaf(e1.y, u1.y, dot0);
        dot0 = fmaf(e1.z, u1.z, dot0);   dot0 = fmaf(e1.w, u1.w, dot0);
        dotd = e0.x * w0.x;              dotd = fmaf(e0.y, w0.y, dotd);
        dotd = fmaf(e0.z, w0.z, dotd);   dotd = fmaf(e0.w, w0.w, dotd);
        dotd = fmaf(e1.x, w1.x, dotd);   dotd = fmaf(e1.y, w1.y, dotd);
        dotd = fmaf(e1.z, w1.z, dotd);   dotd = fmaf(e1.w, w1.w, dotd);

        {
            float send = (lane & 16) ? dot0 : dotd;
            float recv = __shfl_xor_sync(0xffffffffu, send, 16);
            float v = (lane & 16) ? (dotd + recv) : (dot0 + recv);
            #pragma unroll
            for (int o = 8; o; o >>= 1) v += __shfl_xor_sync(0xffffffffu, v, o);
            float other = __shfl_xor_sync(0xffffffffu, v, 16);
            dot0 = (lane & 16) ? other : v;
            dotd = (lane & 16) ? v : other;
        }

        float em = xm_i * xm_j;
        bool am = em > 0.f;

        float sc = am ? (dot0 + c_i) * em * 0.125f : -1e9f;
        float mn = fmaxf(m, sc);
        float alpha = __expf(m - mn);
        float pv = __expf(sc - mn);
        l = l * alpha + pv;
        float pve = pv * em;
        tacc = tacc * alpha + pve;
        s0.x = fmaf(s0.x, alpha, pve * e0.x);
        s0.y = fmaf(s0.y, alpha, pve * e0.y);
        s0.z = fmaf(s0.z, alpha, pve * e0.z);
        s0.w = fmaf(s0.w, alpha, pve * e0.w);
        s1.x = fmaf(s1.x, alpha, pve * e1.x);
        s1.y = fmaf(s1.y, alpha, pve * e1.y);
        s1.z = fmaf(s1.z, alpha, pve * e1.z);
        s1.w = fmaf(s1.w, alpha, pve * e1.w);
        m = mn;

        float o0 = 0.f, o1 = 0.f;
        if (am) {
            float arg = (dotd + dj - di) * em * 0.125f;
            float ai = 1.f / (1.f + __expf(-arg));
            float aj = 1.f - ai;
            o0 = (ai * vnj.x + aj * vni.x) * em;
            o1 = (ai * vnj.y + aj * vni.y) * em;
        }
        __stcg(reinterpret_cast<float2*>(out_e + ((size_t)r * Nn + j) * DHh + 2 * lane),
               make_float2(o0, o1));

        j = jn;
        e0 = ne0; e1 = ne1;
    }

    big[wid * Dd + d0 + 0] = s0.x; big[wid * Dd + d0 + 1] = s0.y;
    big[wid * Dd + d0 + 2] = s0.z; big[wid * Dd + d0 + 3] = s0.w;
    big[wid * Dd + d1 + 0] = s1.x; big[wid * Dd + d1 + 1] = s1.y;
    big[wid * Dd + d1 + 2] = s1.z; big[wid * Dd + d1 + 3] = s1.w;
    if (lane == 0) { mw[wid] = m; lw[wid] = l; tw[wid] = tacc; }
    __syncthreads();

    {
        float gm = mw[0];
        #pragma unroll
        for (int w = 1; w < 8; ++w) gm = fmaxf(gm, mw[w]);
        float gl = 0.f, gt = 0.f, gs = 0.f;
        #pragma unroll
        for (int w = 0; w < 8; ++w) {
            float sc2 = __expf(mw[w] - gm);
            gl = fmaf(lw[w], sc2, gl);
            gt = fmaf(tw[w], sc2, gt);
            gs = fmaf(big[w * Dd + t], sc2, gs);
        }
        float invl = 1.f / gl;
        gsrow[t] = gs * invl;
        if (t == 0) gt_s = gt * invl;
    }

    const float* Q = g_np + 3 * (size_t)BND;
    const float* K = g_np + 4 * (size_t)BND;
    const float* V = g_np + 5 * (size_t)BND;

    if (t < DHh) Q_s[t] = Q[(size_t)r * DHh + t];

    for (int tt = 0; tt < 2; ++tt) {
        __syncthreads();
        for (int idx = t; idx < 128 * 64; idx += 256) {
            int row = idx >> 6, col = idx & 63;
            big[row * 65 + col] = K[(size_t)(b * Nn + tt * 128 + row) * DHh + col];
        }
        __syncthreads();
        int row = t & 127, half = t >> 7;
        float p = 0.f;
        #pragma unroll 8
        for (int d = 0; d < 32; ++d)
            p = fmaf(Q_s[half * 32 + d], big[row * 65 + half * 32 + d], p);
        red[t] = p;
        __syncthreads();
        if (t < 128) att[tt * 128 + t] = red[t] + red[t + 128];
    }
    __syncthreads();

    {
        float xm_j = maskb_s[t];
        bool am = (xm_i * xm_j) > 0.f;
        float lg = am ? att[t] * 0.125f : -1e9f;
        float wmax = lg;
        #pragma unroll
        for (int o = 16; o; o >>= 1)
            wmax = fmaxf(wmax, __shfl_xor_sync(0xffffffffu, wmax, o));
        if (lane == 0) red[wid] = wmax;
        __syncthreads();
        float gmax = red[0];
        #pragma unroll
        for (int w = 1; w < 8; ++w) gmax = fmaxf(gmax, red[w]);
        float ex = __expf(lg - gmax);
        float wsum = ex;
        #pragma unroll
        for (int o = 16; o; o >>= 1)
            wsum += __shfl_xor_sync(0xffffffffu, wsum, o);
        if (lane == 0) red[8 + wid] = wsum;
        __syncthreads();
        float gsum = 0.f;
        #pragma unroll
        for (int w = 0; w < 8; ++w) gsum += red[8 + w];
        att[t] = ex / gsum;
    }
    __syncthreads();

    {
        int q = t >> 6, h = t & 63;
        float acc = 0.f;
        const float* Vb = V + (size_t)(b * Nn + q * 64) * DHh + h;
        #pragma unroll 8
        for (int jj = 0; jj < 64; ++jj)
            acc = fmaf(att[q * 64 + jj], Vb[(size_t)jj * DHh], acc);
        part[q][h] = acc;
    }
    __syncthreads();
    if (t < DHh)
        xsf_s[t] = (part[0][t] + part[1][t] + part[2][t] + part[3][t]) * xm_i;
    __syncthreads();

    {
        int q = t >> 6, h = t & 63;
        float acc = (q == 0) ? gt_s * bv[h] : 0.f;
        #pragma unroll 8
        for (int d = 0; d < 64; ++d)
            acc = fmaf(gsrow[q * 64 + d], Wv[(q * 64 + d) * DHh + h], acc);
        part[q][h] = acc;
    }
    __syncthreads();
    if (t < DHh) xc_s[t] = part[0][t] + part[1][t] + part[2][t] + part[3][t];
    __syncthreads();

    if (t < 128) {
        int half = t >> 6, hh = t & 63;
        float o = (half == 0) ? bmix[hh] : 0.f;
        #pragma unroll 8
        for (int k = 0; k < 64; ++k) {
            float src = (half == 0) ? xc_s[k] : xsf_s[k];
            o = fmaf(src, Wmix[(half * 64 + k) * DHh + hh], o);
        }
        part[half][hh] = o;
    }
    __syncthreads();
    if (t < DHh) out_x[(size_t)r * DHh + t] = part[0][t] + part[1][t];
}

extern "C" void kernel_launch(void* const* d_in, const int* in_sizes, int n_in,
                              void* d_out, int out_size)
{
    const float* x       = (const float*)d_in[0];
    const float* e       = (const float*)d_in[1];
    const float* mask    = (const float*)d_in[2];
    const float* W_n2e_q = (const float*)d_in[3];  const float* b_n2e_q = (const float*)d_in[4];
    const float* W_n2e_k = (const float*)d_in[5];  const float* b_n2e_k = (const float*)d_in[6];
    const float* W_n2e_v = (const float*)d_in[7];  const float* b_n2e_v = (const float*)d_in[8];
    const float* W_e2n_q = (const float*)d_in[9];  const float* b_e2n_q = (const float*)d_in[10];
    const float* W_e2n_k = (const float*)d_in[11]; const float* b_e2n_k = (const float*)d_in[12];
    const float* W_e2n_v = (const float*)d_in[13]; const float* b_e2n_v = (const float*)d_in[14];
    const float* W_n2n_q = (const float*)d_in[15]; const float* b_n2n_q = (const float*)d_in[16];
    const float* W_n2n_k = (const float*)d_in[17]; const float* b_n2n_k = (const float*)d_in[18];
    const float* W_n2n_v = (const float*)d_in[19]; const float* b_n2n_v = (const float*)d_in[20];
    const float* W_mix   = (const float*)d_in[21]; const float* b_mix   = (const float*)d_in[22];

    float* out   = (float*)d_out;
    float* out_x = out;
    float* out_e = out + (size_t)Bn * Nn * DHh;

    transpose_w_kernel<<<DHh, Dd>>>(W_n2e_k, W_e2n_q);

    fold_kernel<<<65, 256>>>(W_n2e_q, W_e2n_k, b_n2e_q, b_e2n_k);

    megaproj_kernel<<<dim3(128, 14), 256>>>(x, mask,
        W_n2e_q, b_n2e_q,   // slot0 = Qn
        W_e2n_k, b_e2n_k,   // slot1 = Kn
        W_e2n_v, b_e2n_v,   // slot2 = Vn
        W_n2n_q, b_n2n_q,   // slot3 = Q
        W_n2n_k, b_n2n_k,   // slot4 = K
        W_n2n_v, b_n2n_v,   // slot5 = V
        b_n2e_k, b_e2n_q);

    fused_kernel<<<BNr, 256>>>(e, mask,
        W_n2e_v, b_n2e_v, W_mix, b_mix, out_e, out_x);
}

// round 13
// speedup vs baseline: 1.0852x; 1.0852x over previous
#include <cuda_runtime.h>
#include <math.h>

#define Bn 8
#define Nn 256
#define Dd 256
#define DHh 64
#define BND (Bn * Nn * DHh)      // 131072
#define BNr (Bn * Nn)            // 2048

// scratch: Qn,Kn,Vn,Q,K,V
__device__ float g_np[6 * BND];
// folded-weight per-row vectors
__device__ float g_u[BNr * Dd];    // Wk_n2e @ Qn_i
__device__ float g_v[BNr * Dd];    // Wq_e2n @ Kn_j
__device__ float g_c[BNr];         // bk_n2e . Qn_i
__device__ float g_d[BNr];         // bq_e2n . Kn_j
// transposed weights (h-major)
__device__ float g_Wkt[DHh * Dd];
__device__ float g_Wqt[DHh * Dd];
// softmax-weighted e sum and scalar
__device__ float g_s[BNr * Dd];
__device__ float g_t[BNr];

// ------------------------------------------------------------------
// 6 projections of x + (y==6, x<64) weight transpose.  (R10 verbatim)
// grid = (128 row-tiles, 7), block = 256. 16 rows/block.
// ------------------------------------------------------------------
__global__ void proj_x_kernel(
    const float* __restrict__ x, const float* __restrict__ mask,
    const float* __restrict__ W0, const float* __restrict__ b0,
    const float* __restrict__ W1, const float* __restrict__ b1,
    const float* __restrict__ W2, const float* __restrict__ b2,
    const float* __restrict__ W3, const float* __restrict__ b3,
    const float* __restrict__ W4, const float* __restrict__ b4,
    const float* __restrict__ W5, const float* __restrict__ b5,
    const float* __restrict__ Wkfold, const float* __restrict__ Wqfold)
{
    int p  = blockIdx.y;
    int t  = threadIdx.x;

    if (p == 6) {
        if (blockIdx.x < 64) {
            int h = blockIdx.x;
            g_Wkt[h * Dd + t] = Wkfold[t * DHh + h];
            g_Wqt[h * Dd + t] = Wqfold[t * DHh + h];
        }
        return;
    }

    int r0 = blockIdx.x * 16;
    __shared__ float xs[16][Dd];
    __shared__ float msk[16];

    {
        const float4* src = reinterpret_cast<const float4*>(x + (size_t)r0 * Dd);
        float4* dst = reinterpret_cast<float4*>(&xs[0][0]);
        #pragma unroll
        for (int i = 0; i < 4; ++i)
            dst[t + i * 256] = src[t + i * 256];
        if (t < 16) msk[t] = mask[r0 + t];
    }
    __syncthreads();

    const float* W;
    const float* bb;
    switch (p) {
        case 0: W = W0; bb = b0; break;
        case 1: W = W1; bb = b1; break;
        case 2: W = W2; bb = b2; break;
        case 3: W = W3; bb = b3; break;
        case 4: W = W4; bb = b4; break;
        default: W = W5; bb = b5; break;
    }

    int h = t & 63, rg = t >> 6;
    int rb = rg * 4;
    float bias = bb[h];
    float a0 = bias, a1 = bias, a2 = bias, a3 = bias;

    #pragma unroll 2
    for (int k = 0; k < Dd; k += 4) {
        float w0 = W[(k + 0) * DHh + h];
        float w1 = W[(k + 1) * DHh + h];
        float w2 = W[(k + 2) * DHh + h];
        float w3 = W[(k + 3) * DHh + h];
        float4 x0 = *reinterpret_cast<const float4*>(&xs[rb + 0][k]);
        float4 x1 = *reinterpret_cast<const float4*>(&xs[rb + 1][k]);
        float4 x2 = *reinterpret_cast<const float4*>(&xs[rb + 2][k]);
        float4 x3 = *reinterpret_cast<const float4*>(&xs[rb + 3][k]);
        a0 = fmaf(x0.x, w0, a0); a0 = fmaf(x0.y, w1, a0);
        a0 = fmaf(x0.z, w2, a0); a0 = fmaf(x0.w, w3, a0);
        a1 = fmaf(x1.x, w0, a1); a1 = fmaf(x1.y, w1, a1);
        a1 = fmaf(x1.z, w2, a1); a1 = fmaf(x1.w, w3, a1);
        a2 = fmaf(x2.x, w0, a2); a2 = fmaf(x2.y, w1, a2);
        a2 = fmaf(x2.z, w2, a2); a2 = fmaf(x2.w, w3, a2);
        a3 = fmaf(x3.x, w0, a3); a3 = fmaf(x3.y, w1, a3);
        a3 = fmaf(x3.z, w2, a3); a3 = fmaf(x3.w, w3, a3);
    }

    float* dst = g_np + (size_t)p * BND + (size_t)(r0 + rb) * DHh + h;
    dst[0 * DHh] = a0 * msk[rb + 0];
    dst[1 * DHh] = a1 * msk[rb + 1];
    dst[2 * DHh] = a2 * msk[rb + 2];
    dst[3 * DHh] = a3 * msk[rb + 3];
}

// ------------------------------------------------------------------
// u/v GEMM + (y==0) bias dots.  (R10 verbatim)  grid (64,4), block 256.
// ------------------------------------------------------------------
__global__ void make_uv_kernel(const float* __restrict__ bk,
                               const float* __restrict__ bq)
{
    int r0 = blockIdx.x * 32;
    int d0 = blockIdx.y * 64;
    int t  = threadIdx.x;

    __shared__ float qn[32][DHh];
    __shared__ float kn[32][DHh];

    {
        const float4* srcq = reinterpret_cast<const float4*>(g_np + (size_t)r0 * DHh);
        const float4* srck = reinterpret_cast<const float4*>(g_np + (size_t)BND + (size_t)r0 * DHh);
        float4* dq = reinterpret_cast<float4*>(&qn[0][0]);
        float4* dk = reinterpret_cast<float4*>(&kn[0][0]);
        dq[t] = srcq[t];
        dk[t] = srck[t];
        dq[t + 256] = srcq[t + 256];
        dk[t + 256] = srck[t + 256];
    }
    __syncthreads();

    int dd = t & 63, rg = t >> 6;
    int rb = rg * 8;
    int d  = d0 + dd;

    {
        float au[8];
        #pragma unroll
        for (int i = 0; i < 8; ++i) au[i] = 0.f;
        #pragma unroll 2
        for (int h = 0; h < DHh; h += 4) {
            float w0 = g_Wkt[(h + 0) * Dd + d];
            float w1 = g_Wkt[(h + 1) * Dd + d];
            float w2 = g_Wkt[(h + 2) * Dd + d];
            float w3 = g_Wkt[(h + 3) * Dd + d];
            #pragma unroll
            for (int i = 0; i < 8; ++i) {
                float4 qv = *reinterpret_cast<const float4*>(&qn[rb + i][h]);
                au[i] = fmaf(qv.x, w0, au[i]);
                au[i] = fmaf(qv.y, w1, au[i]);
                au[i] = fmaf(qv.z, w2, au[i]);
                au[i] = fmaf(qv.w, w3, au[i]);
            }
        }
        #pragma unroll
        for (int i = 0; i < 8; ++i)
            g_u[(size_t)(r0 + rb + i) * Dd + d] = au[i];
    }
    {
        float av[8];
        #pragma unroll
        for (int i = 0; i < 8; ++i) av[i] = 0.f;
        #pragma unroll 2
        for (int h = 0; h < DHh; h += 4) {
            float w0 = g_Wqt[(h + 0) * Dd + d];
            float w1 = g_Wqt[(h + 1) * Dd + d];
            float w2 = g_Wqt[(h + 2) * Dd + d];
            float w3 = g_Wqt[(h + 3) * Dd + d];
            #pragma unroll
            for (int i = 0; i < 8; ++i) {
                float4 kv = *reinterpret_cast<const float4*>(&kn[rb + i][h]);
                av[i] = fmaf(kv.x, w0, av[i]);
                av[i] = fmaf(kv.y, w1, av[i]);
                av[i] = fmaf(kv.z, w2, av[i]);
                av[i] = fmaf(kv.w, w3, av[i]);
            }
        }
        #pragma unroll
        for (int i = 0; i < 8; ++i)
            g_v[(size_t)(r0 + rb + i) * Dd + d] = av[i];
    }

    if (blockIdx.y == 0) {
        if (t < 32) {
            float sc = 0.f;
            #pragma unroll 8
            for (int h = 0; h < DHh; ++h) sc = fmaf(bk[h], qn[t][h], sc);
            g_c[r0 + t] = sc;
        } else if (t < 64) {
            int row = t - 32;
            float sd = 0.f;
            #pragma unroll 8
            for (int h = 0; h < DHh; ++h) sd = fmaf(bq[h], kn[row][h], sd);
            g_d[r0 + row] = sd;
        }
    }
}

// ------------------------------------------------------------------
// Edge kernel — EXACT Round-4-measured loop (135us). (R11 verbatim)
// ------------------------------------------------------------------
__global__ void edge_kernel(const float* __restrict__ e,
                            const float* __restrict__ mask,
                            float* __restrict__ out_e)
{
    int r = blockIdx.x;
    int b = r >> 8;
    int t = threadIdx.x;
    int wid = t >> 5, lane = t & 31;

    const float* Vn = g_np + 2 * (size_t)BND;

    int d0 = 4 * lane;
    int d1 = 128 + 4 * lane;

    const float4 u0  = *reinterpret_cast<const float4*>(g_u + (size_t)r * Dd + d0);
    const float4 u1  = *reinterpret_cast<const float4*>(g_u + (size_t)r * Dd + d1);
    const float4 vi0 = *reinterpret_cast<const float4*>(g_v + (size_t)r * Dd + d0);
    const float4 vi1 = *reinterpret_cast<const float4*>(g_v + (size_t)r * Dd + d1);
    const float c_i  = g_c[r];
    const float di   = g_d[r];
    const float xm_i = mask[r];
    const float2 vni = *reinterpret_cast<const float2*>(Vn + (size_t)r * DHh + 2 * lane);

    float m = -INFINITY, l = 0.f, tacc = 0.f;
    float4 s0 = make_float4(0.f, 0.f, 0.f, 0.f);
    float4 s1 = make_float4(0.f, 0.f, 0.f, 0.f);

    const float* erow = e + (size_t)r * Nn * Dd;

    int j = wid;
    float4 e0 = __ldcs(reinterpret_cast<const float4*>(erow + (size_t)j * Dd + d0));
    float4 e1 = __ldcs(reinterpret_cast<const float4*>(erow + (size_t)j * Dd + d1));
    float4 vj0 = *reinterpret_cast<const float4*>(g_v + (size_t)(b * Nn + j) * Dd + d0);
    float4 vj1 = *reinterpret_cast<const float4*>(g_v + (size_t)(b * Nn + j) * Dd + d1);
    float2 vnj = *reinterpret_cast<const float2*>(Vn + (size_t)(b * Nn + j) * DHh + 2 * lane);
    float xm_j = mask[b * Nn + j];
    float dj   = g_d[b * Nn + j];

    for (; j < Nn; ) {
        int jn = j + 8;
        float4 ne0, ne1, nvj0, nvj1; float2 nvnj; float nxm_j = 0.f, ndj = 0.f;
        if (jn < Nn) {
            ne0 = __ldcs(reinterpret_cast<const float4*>(erow + (size_t)jn * Dd + d0));
            ne1 = __ldcs(reinterpret_cast<const float4*>(erow + (size_t)jn * Dd + d1));
            nvj0 = *reinterpret_cast<const float4*>(g_v + (size_t)(b * Nn + jn) * Dd + d0);
            nvj1 = *reinterpret_cast<const float4*>(g_v + (size_t)(b * Nn + jn) * Dd + d1);
            nvnj = *reinterpret_cast<const float2*>(Vn + (size_t)(b * Nn + jn) * DHh + 2 * lane);
            nxm_j = mask[b * Nn + jn];
            ndj   = g_d[b * Nn + jn];
        }

        float4 w0, w1;
        w0.x = vj0.x - vi0.x; w0.y = vj0.y - vi0.y;
        w0.z = vj0.z - vi0.z; w0.w = vj0.w - vi0.w;
        w1.x = vj1.x - vi1.x; w1.y = vj1.y - vi1.y;
        w1.z = vj1.z - vi1.z; w1.w = vj1.w - vi1.w;

        float dot0, dotd;
        dot0 = e0.x * u0.x;              dot0 = fmaf(e0.y, u0.y, dot0);
        dot0 = fmaf(e0.z, u0.z, dot0);   dot0 = fmaf(e0.w, u0.w, dot0);
        dot0 = fmaf(e1.x, u1.x, dot0);   dot0 = fmaf(e1.y, u1.y, dot0);
        dot0 = fmaf(e1.z, u1.z, dot0);   dot0 = fmaf(e1.w, u1.w, dot0);
        dotd = e0.x * w0.x;              dotd = fmaf(e0.y, w0.y, dotd);
        dotd = fmaf(e0.z, w0.z, dotd);   dotd = fmaf(e0.w, w0.w, dotd);
        dotd = fmaf(e1.x, w1.x, dotd);   dotd = fmaf(e1.y, w1.y, dotd);
        dotd = fmaf(e1.z, w1.z, dotd);   dotd = fmaf(e1.w, w1.w, dotd);

        #pragma unroll
        for (int o = 16; o; o >>= 1) {
            dot0 += __shfl_xor_sync(0xffffffffu, dot0, o);
            dotd += __shfl_xor_sync(0xffffffffu, dotd, o);
        }

        float em = xm_i * xm_j;
        bool am = em > 0.f;

        float sc = am ? (dot0 + c_i) * em * 0.125f : -1e9f;
        float mn = fmaxf(m, sc);
        float alpha = __expf(m - mn);
        float pv = __expf(sc - mn);
        l = l * alpha + pv;
        float pve = pv * em;
        tacc = tacc * alpha + pve;
        s0.x = fmaf(s0.x, alpha, pve * e0.x);
        s0.y = fmaf(s0.y, alpha, pve * e0.y);
        s0.z = fmaf(s0.z, alpha, pve * e0.z);
        s0.w = fmaf(s0.w, alpha, pve * e0.w);
        s1.x = fmaf(s1.x, alpha, pve * e1.x);
        s1.y = fmaf(s1.y, alpha, pve * e1.y);
        s1.z = fmaf(s1.z, alpha, pve * e1.z);
        s1.w = fmaf(s1.w, alpha, pve * e1.w);
        m = mn;

        float o0 = 0.f, o1 = 0.f;
        if (am) {
            float arg = (dotd + dj - di) * em * 0.125f;
            float ai = 1.f / (1.f + __expf(-arg));
            float aj = 1.f - ai;
            o0 = (ai * vnj.x + aj * vni.x) * em;
            o1 = (ai * vnj.y + aj * vni.y) * em;
        }
        __stcg(reinterpret_cast<float2*>(out_e + ((size_t)r * Nn + j) * DHh + 2 * lane),
               make_float2(o0, o1));

        j = jn;
        e0 = ne0; e1 = ne1; vj0 = nvj0; vj1 = nvj1; vnj = nvnj;
        xm_j = nxm_j; dj = ndj;
    }

    __shared__ float s_sm[8][Dd];
    __shared__ float mw[8], lw[8], tw[8];
    s_sm[wid][d0 + 0] = s0.x; s_sm[wid][d0 + 1] = s0.y;
    s_sm[wid][d0 + 2] = s0.z; s_sm[wid][d0 + 3] = s0.w;
    s_sm[wid][d1 + 0] = s1.x; s_sm[wid][d1 + 1] = s1.y;
    s_sm[wid][d1 + 2] = s1.z; s_sm[wid][d1 + 3] = s1.w;
    if (lane == 0) { mw[wid] = m; lw[wid] = l; tw[wid] = tacc; }
    __syncthreads();

    float gm = mw[0];
    #pragma unroll
    for (int w = 1; w < 8; ++w) gm = fmaxf(gm, mw[w]);
    float gl = 0.f, gt = 0.f, gs = 0.f;
    #pragma unroll
    for (int w = 0; w < 8; ++w) {
        float sc2 = __expf(mw[w] - gm);
        gl = fmaf(lw[w], sc2, gl);
        gt = fmaf(tw[w], sc2, gt);
        gs = fmaf(s_sm[w][t], sc2, gs);
    }
    float invl = 1.f / gl;
    g_s[(size_t)r * Dd + t] = gs * invl;
    if (t == 0) g_t[r] = gt * invl;
}

// ------------------------------------------------------------------
// Tail: warp-per-row, ZERO block syncs. grid = Bn*32 = 256, block 256.
// Each warp owns row r: self-attn logits + softmax (registers),
// PV / x_cross / mix via shuffle-broadcast + coalesced float2 loads.
// ------------------------------------------------------------------
__global__ void tail_kernel(const float* __restrict__ mask,
                            const float* __restrict__ Wv,
                            const float* __restrict__ bv,
                            const float* __restrict__ Wmix,
                            const float* __restrict__ bmix,
                            float* __restrict__ out_x)
{
    int blk = blockIdx.x;
    int b = blk >> 5;
    int rowbase = (blk & 31) * 8;
    int t = threadIdx.x, wid = t >> 5, lane = t & 31;
    int r = b * Nn + rowbase + wid;
    int bN = b * Nn;
    int h0 = 2 * lane;

    __shared__ float Qs[8][DHh];

    const float* Q = g_np + 3 * (size_t)BND;
    const float* K = g_np + 4 * (size_t)BND;
    const float* V = g_np + 5 * (size_t)BND;

    // load Q row into per-warp smem
    {
        float2 qv = *reinterpret_cast<const float2*>(Q + (size_t)r * DHh + h0);
        Qs[wid][h0] = qv.x; Qs[wid][h0 + 1] = qv.y;
    }
    __syncwarp();

    float xm_i = mask[r];

    // ---- logits: lane owns j = jj*32 + lane ----
    float p[8];
    float m = -INFINITY;
    #pragma unroll
    for (int jj = 0; jj < 8; ++jj) {
        int j = jj * 32 + lane;
        const float4* Krow = reinterpret_cast<const float4*>(K + (size_t)(bN + j) * DHh);
        float acc = 0.f;
        #pragma unroll
        for (int k = 0; k < 16; ++k) {
            float4 kv = Krow[k];
            acc = fmaf(kv.x, Qs[wid][4 * k + 0], acc);
            acc = fmaf(kv.y, Qs[wid][4 * k + 1], acc);
            acc = fmaf(kv.z, Qs[wid][4 * k + 2], acc);
            acc = fmaf(kv.w, Qs[wid][4 * k + 3], acc);
        }
        bool am = (xm_i * mask[bN + j]) > 0.f;
        p[jj] = am ? acc * 0.125f : -1e9f;
        m = fmaxf(m, p[jj]);
    }
    #pragma unroll
    for (int o = 16; o; o >>= 1)
        m = fmaxf(m, __shfl_xor_sync(0xffffffffu, m, o));
    float s = 0.f;
    #pragma unroll
    for (int jj = 0; jj < 8; ++jj) { p[jj] = __expf(p[jj] - m); s += p[jj]; }
    #pragma unroll
    for (int o = 16; o; o >>= 1)
        s += __shfl_xor_sync(0xffffffffu, s, o);
    float inv = 1.f / s;
    #pragma unroll
    for (int jj = 0; jj < 8; ++jj) p[jj] *= inv;

    // ---- PV: lane owns head dims h0, h0+1 ----
    float xs0 = 0.f, xs1 = 0.f;
    #pragma unroll
    for (int jj = 0; jj < 8; ++jj) {
        #pragma unroll 8
        for (int src = 0; src < 32; ++src) {
            float pj = __shfl_sync(0xffffffffu, p[jj], src);
            float2 v = *reinterpret_cast<const float2*>(
                V + (size_t)(bN + jj * 32 + src) * DHh + h0);
            xs0 = fmaf(pj, v.x, xs0);
            xs1 = fmaf(pj, v.y, xs1);
        }
    }
    xs0 *= xm_i; xs1 *= xm_i;

    // ---- x_cross: lane owns gs dims 8*lane..8*lane+7 ----
    float gsl[8];
    {
        const float4* gsp = reinterpret_cast<const float4*>(g_s + (size_t)r * Dd + 8 * lane);
        float4 a = gsp[0], bq = gsp[1];
        gsl[0] = a.x; gsl[1] = a.y; gsl[2] = a.z; gsl[3] = a.w;
        gsl[4] = bq.x; gsl[5] = bq.y; gsl[6] = bq.z; gsl[7] = bq.w;
    }
    float gt = g_t[r];
    float xc0 = gt * bv[h0], xc1 = gt * bv[h0 + 1];
    #pragma unroll
    for (int dd = 0; dd < 8; ++dd) {
        #pragma unroll 8
        for (int src = 0; src < 32; ++src) {
            float gv = __shfl_sync(0xffffffffu, gsl[dd], src);
            int d = 8 * src + dd;
            float2 w = *reinterpret_cast<const float2*>(Wv + (size_t)d * DHh + h0);
            xc0 = fmaf(gv, w.x, xc0);
            xc1 = fmaf(gv, w.y, xc1);
        }
    }

    // ---- mix: out = [xc, xs] @ Wmix + bmix ----
    float o0 = bmix[h0], o1 = bmix[h0 + 1];
    #pragma unroll 8
    for (int src = 0; src < 32; ++src) {
        float a0 = __shfl_sync(0xffffffffu, xc0, src);
        float a1 = __shfl_sync(0xffffffffu, xc1, src);
        int k = 2 * src;
        float2 w0 = *reinterpret_cast<const float2*>(Wmix + (size_t)k * DHh + h0);
        float2 w1 = *reinterpret_cast<const float2*>(Wmix + (size_t)(k + 1) * DHh + h0);
        o0 = fmaf(a0, w0.x, o0); o1 = fmaf(a0, w0.y, o1);
        o0 = fmaf(a1, w1.x, o0); o1 = fmaf(a1, w1.y, o1);
        float s0 = __shfl_sync(0xffffffffu, xs0, src);
        float s1 = __shfl_sync(0xffffffffu, xs1, src);
        float2 v0 = *reinterpret_cast<const float2*>(Wmix + (size_t)(DHh + k) * DHh + h0);
        float2 v1 = *reinterpret_cast<const float2*>(Wmix + (size_t)(DHh + k + 1) * DHh + h0);
        o0 = fmaf(s0, v0.x, o0); o1 = fmaf(s0, v0.y, o1);
        o0 = fmaf(s1, v1.x, o0); o1 = fmaf(s1, v1.y, o1);
    }
    *reinterpret_cast<float2*>(out_x + (size_t)r * DHh + h0) = make_float2(o0, o1);
}

extern "C" void kernel_launch(void* const* d_in, const int* in_sizes, int n_in,
                              void* d_out, int out_size)
{
    const float* x       = (const float*)d_in[0];
    const float* e       = (const float*)d_in[1];
    const float* mask    = (const float*)d_in[2];
    const float* W_n2e_q = (const float*)d_in[3];  const float* b_n2e_q = (const float*)d_in[4];
    const float* W_n2e_k = (const float*)d_in[5];  const float* b_n2e_k = (const float*)d_in[6];
    const float* W_n2e_v = (const float*)d_in[7];  const float* b_n2e_v = (const float*)d_in[8];
    const float* W_e2n_q = (const float*)d_in[9];  const float* b_e2n_q = (const float*)d_in[10];
    const float* W_e2n_k = (const float*)d_in[11]; const float* b_e2n_k = (const float*)d_in[12];
    const float* W_e2n_v = (const float*)d_in[13]; const float* b_e2n_v = (const float*)d_in[14];
    const float* W_n2n_q = (const float*)d_in[15]; const float* b_n2n_q = (const float*)d_in[16];
    const float* W_n2n_k = (const float*)d_in[17]; const float* b_n2n_k = (const float*)d_in[18];
    const float* W_n2n_v = (const float*)d_in[19]; const float* b_n2n_v = (const float*)d_in[20];
    const float* W_mix   = (const float*)d_in[21]; const float* b_mix   = (const float*)d_in[22];

    float* out   = (float*)d_out;
    float* out_x = out;
    float* out_e = out + (size_t)Bn * Nn * DHh;

    proj_x_kernel<<<dim3(128, 7), 256>>>(x, mask,
        W_n2e_q, b_n2e_q,   // slot0 = Qn
        W_e2n_k, b_e2n_k,   // slot1 = Kn
        W_e2n_v, b_e2n_v,   // slot2 = Vn
        W_n2n_q, b_n2n_q,   // slot3 = Q
        W_n2n_k, b_n2n_k,   // slot4 = K
        W_n2n_v, b_n2n_v,   // slot5 = V
        W_n2e_k, W_e2n_q);

    make_uv_kernel<<<dim3(64, 4), 256>>>(b_n2e_k, b_e2n_q);

    edge_kernel<<<BNr, 256>>>(e, mask, out_e);

    tail_kernel<<<Bn * 32, 256>>>(mask, W_n2e_v, b_n2e_v, W_mix, b_mix, out_x);
}